// round 14
// baseline (speedup 1.0000x reference)
#include <cuda_runtime.h>
#include <cuda_fp16.h>
#include <cstdint>

#define B_  2
#define N_  2048
#define D_  1024
#define H_  16
#define DH_ 64
#define M_  (B_ * N_)
#define QSCALE 0.04508422f   // (1/32) * log2(e)

// ---------------- scratch (packed fp16x2 in uint32) ----------------
__device__ uint32_t g_Xhi  [M_ * D_ / 2];
__device__ uint32_t g_Wqhi [D_ * D_ / 2];
__device__ uint32_t g_Wkvhi[2 * DH_ * D_ / 2];   // rows 0-63 = Wk, 64-127 = Wv
__device__ uint32_t g_Wfhi [D_ * D_ / 2];
__device__ uint32_t g_Qhi  [M_ * D_ / 2];
__device__ uint32_t g_Khi  [M_ * DH_ / 2];
__device__ uint32_t g_Vhi  [M_ * DH_ / 2];
__device__ uint32_t g_AOhi [M_ * D_ / 2];

__device__ __forceinline__ uint32_t smem_u32(const void* p) {
    uint32_t a;
    asm("{ .reg .u64 t; cvta.to.shared.u64 t, %1; cvt.u32.u64 %0, t; }"
        : "=r"(a) : "l"(p));
    return a;
}

__device__ __forceinline__ float ex2f(float t) {
    float r;
    asm("ex2.approx.f32 %0, %1;" : "=f"(r) : "f"(t));
    return r;
}

__device__ __forceinline__ uint32_t packh2(float a, float b) {
    __half2 t = __floats2half2_rn(a, b);
    return *(uint32_t*)&t;
}

#define LDM4(r, addr)                                                         \
    asm volatile("ldmatrix.sync.aligned.m8n8.x4.shared.b16 {%0,%1,%2,%3}, [%4];" \
        : "=r"((r)[0]), "=r"((r)[1]), "=r"((r)[2]), "=r"((r)[3])              \
        : "r"(addr))

#define LDM4T(r, addr)                                                        \
    asm volatile("ldmatrix.sync.aligned.m8n8.x4.trans.shared.b16 {%0,%1,%2,%3}, [%4];" \
        : "=r"((r)[0]), "=r"((r)[1]), "=r"((r)[2]), "=r"((r)[3])              \
        : "r"(addr))

#define MMA16816(d, a, b0, b1)                                                \
    asm volatile("mma.sync.aligned.m16n8k16.row.col.f32.f16.f16.f32 "         \
        "{%0,%1,%2,%3},{%4,%5,%6,%7},{%8,%9},{%0,%1,%2,%3};"                  \
        : "+f"((d)[0]), "+f"((d)[1]), "+f"((d)[2]), "+f"((d)[3])              \
        : "r"((a)[0]), "r"((a)[1]), "r"((a)[2]), "r"((a)[3]),                 \
          "r"(b0), "r"(b1))

#define CP16(dst, src)                                                        \
    asm volatile("cp.async.cg.shared.global [%0], [%1], 16;"                  \
        :: "r"(dst), "l"(src))
#define CPCOMMIT() asm volatile("cp.async.commit_group;" ::: "memory")
#define CPWAIT1()  asm volatile("cp.async.wait_group 1;"  ::: "memory")

// xor-swizzled 128B-row smem offset (row r, 16B-oct o) — conflict-free both ways
__device__ __forceinline__ uint32_t swz(int r, int o) {
    return (uint32_t)(r * 128 + ((o ^ (r & 7)) << 4));
}

// ============================================================================
// split: fp32 -> packed fp16. Segments: X | Wq | Wk->Wkv[0:64] | Wv->Wkv[64:] | Wfc
// ============================================================================
#define OX  (M_ * D_ / 8)
#define OWQ (D_ * D_ / 8)
#define OWK (DH_ * D_ / 8)
#define OTOT (OX + OWQ + 2 * OWK + OWQ)

__global__ __launch_bounds__(256) void split_hi(
    const float* __restrict__ x,  const float* __restrict__ Wq,
    const float* __restrict__ Wk, const float* __restrict__ Wv,
    const float* __restrict__ Wfc,
    uint32_t* __restrict__ Xhi,  uint32_t* __restrict__ Wqhi,
    uint32_t* __restrict__ Wkvhi, uint32_t* __restrict__ Wfhi)
{
    int i = blockIdx.x * 256 + threadIdx.x;
    if (i >= OTOT) return;
    const float* src; uint32_t* hi; int j, dj;
    if (i < OX)                      { j = i;                      src = x;   hi = Xhi;   dj = j; }
    else if (i < OX + OWQ)           { j = i - OX;                 src = Wq;  hi = Wqhi;  dj = j; }
    else if (i < OX + OWQ + OWK)     { j = i - OX - OWQ;           src = Wk;  hi = Wkvhi; dj = j; }
    else if (i < OX + OWQ + 2 * OWK) { j = i - OX - OWQ - OWK;     src = Wv;  hi = Wkvhi; dj = j + OWK; }
    else                             { j = i - OX - OWQ - 2 * OWK; src = Wfc; hi = Wfhi;  dj = j; }
    const float4* s = (const float4*)src + (size_t)j * 2;
    float4 a = s[0], b = s[1];
    uint4 h;
    h.x = packh2(a.x, a.y); h.y = packh2(a.z, a.w);
    h.z = packh2(b.x, b.y); h.w = packh2(b.z, b.w);
    ((uint4*)hi)[dj] = h;
}

// ============================================================================
// Big-tile fp16 GEMM: 256x128 CTA tile, 512 threads (16 warps: 4 wm x 4 wn),
// K-step 64, 3-stage cp.async, xor-swizzled 128B-row smem.
// EPI 0: QKV (bx<8 -> Qhi cols bx*128, scaled; bx==8 -> K cols 0-63 / V 64-127)
// EPI 1: FC  (fp32 out + bias), B = Wfhi.
// ============================================================================
template <int EPI>
__global__ __launch_bounds__(512) void gemm_big(
    const uint32_t* __restrict__ Ahi, const uint32_t* __restrict__ Bq,
    const uint32_t* __restrict__ Bkv,
    const float* __restrict__ bias, float* __restrict__ C,
    uint32_t* __restrict__ Qhi, uint32_t* __restrict__ Khi,
    uint32_t* __restrict__ Vhi)
{
    extern __shared__ char smc[];
    constexpr int ASZ = 256 * 128, BSZ = 128 * 128, STAGE = ASZ + BSZ;
    const uint32_t smb = smem_u32(smc);

    const int tid = threadIdx.x, lane = tid & 31, warp = tid >> 5;
    const int wm = warp & 3, wn = warp >> 2;            // 4 x 4
    const int m0 = blockIdx.y * 256;
    const int bx = blockIdx.x;

    const uint32_t* Bp;
    if (EPI == 0) Bp = (bx < 8) ? (Bq + (size_t)bx * 128 * (D_ / 2)) : Bkv;
    else          Bp = Bq + (size_t)bx * 128 * (D_ / 2);

    const int arow = ((lane >> 3) & 1) * 8 + (lane & 7);
    const int lrow = ((lane >> 1) & 8) + (lane & 7);
    const int chA  = (lane >> 4) & 1;
    const int chK  = (lane >> 3) & 1;

    float acc[4][4][4];                                  // 64 regs
#pragma unroll
    for (int mi = 0; mi < 4; mi++)
#pragma unroll
        for (int f = 0; f < 4; f++)
#pragma unroll
            for (int q = 0; q < 4; q++) acc[mi][f][q] = 0.f;

    const int K8 = D_ / 8;
    const int nkt = D_ / 64;

    auto load_stage = [&](int s, int it) {
        const uint32_t sb = smb + s * STAGE;
        const int ob = it * 8;
#pragma unroll
        for (int t = 0; t < 4; t++) {          // A: 2048 octs / 512 thr
            int ol = tid + t * 512;
            int r = ol >> 3, o = ol & 7;
            CP16(sb + swz(r, o), (const uint4*)Ahi + (size_t)(m0 + r) * K8 + ob + o);
        }
#pragma unroll
        for (int t = 0; t < 2; t++) {          // B: 1024 octs / 512 thr
            int ol = tid + t * 512;
            int r = ol >> 3, o = ol & 7;
            CP16(sb + ASZ + swz(r, o), (const uint4*)Bp + (size_t)r * K8 + ob + o);
        }
    };

    load_stage(0, 0); CPCOMMIT();
    load_stage(1, 1); CPCOMMIT();

    for (int it = 0; it < nkt; it++) {
        CPWAIT1();
        __syncthreads();
        if (it + 2 < nkt) load_stage((it + 2) % 3, it + 2);
        CPCOMMIT();

        const uint32_t sA = smb + (it % 3) * STAGE;
        const uint32_t sB = sA + ASZ;

#pragma unroll
        for (int kb = 0; kb < 4; kb++) {
            uint32_t ah[4][4];
#pragma unroll
            for (int mi = 0; mi < 4; mi++) {
                int r = wm * 64 + mi * 16 + arow;
                LDM4(ah[mi], sA + (uint32_t)(r * 128 +
                             (((kb * 2 + chA) ^ (r & 7)) << 4)));
            }
#pragma unroll
            for (int j = 0; j < 2; j++) {
                uint32_t bh[4];
                int brow = wn * 32 + j * 16 + lrow;
                LDM4(bh, sB + (uint32_t)(brow * 128 +
                         (((kb * 2 + chK) ^ (brow & 7)) << 4)));
#pragma unroll
                for (int mi = 0; mi < 4; mi++) {
                    MMA16816(acc[mi][j * 2],     ah[mi], bh[0], bh[1]);
                    MMA16816(acc[mi][j * 2 + 1], ah[mi], bh[2], bh[3]);
                }
            }
        }
    }

    // epilogue
#pragma unroll
    for (int mi = 0; mi < 4; mi++)
#pragma unroll
        for (int f = 0; f < 4; f++) {
            int row = m0 + wm * 64 + mi * 16 + (lane >> 2);
            int lc  = wn * 32 + f * 8 + (lane & 3) * 2;
            float v0 = acc[mi][f][0], v1 = acc[mi][f][1];
            float v2 = acc[mi][f][2], v3 = acc[mi][f][3];
            if (EPI == 0) {
                if (bx < 8) {
                    int col = bx * 128 + lc;
                    Qhi[((size_t)row * D_ + col) >> 1] =
                        packh2(v0 * QSCALE, v1 * QSCALE);
                    Qhi[((size_t)(row + 8) * D_ + col) >> 1] =
                        packh2(v2 * QSCALE, v3 * QSCALE);
                } else if (lc < 64) {
                    Khi[((size_t)row * DH_ + lc) >> 1]       = packh2(v0, v1);
                    Khi[((size_t)(row + 8) * DH_ + lc) >> 1] = packh2(v2, v3);
                } else {
                    Vhi[((size_t)row * DH_ + lc - 64) >> 1]       = packh2(v0, v1);
                    Vhi[((size_t)(row + 8) * DH_ + lc - 64) >> 1] = packh2(v2, v3);
                }
            } else {
                int col = bx * 128 + lc;
                float b0 = bias[col], b1 = bias[col + 1];
                *(float2*)&C[(size_t)row * D_ + col] =
                    make_float2(v0 + b0, v1 + b1);
                *(float2*)&C[(size_t)(row + 8) * D_ + col] =
                    make_float2(v2 + b0, v3 + b1);
            }
        }
}

// ============================================================================
// Flash attention: CTA = 64 q-rows x 4 heads (K/V loaded ONCE per CTA for all
// 4 heads). 256 threads, 8 warps: warp = 32 rows of head (warp&3), half (warp>>2).
// Shift-free softmax, tensor-pipe row sums, 3-stage cp.async.
// ============================================================================
__global__ __launch_bounds__(256) void flash_h(
    const uint32_t* __restrict__ Qhi, const uint32_t* __restrict__ Khi,
    const uint32_t* __restrict__ Vhi, const int* __restrict__ mask,
    uint32_t* __restrict__ AOhi)
{
    extern __shared__ char smf[];
    const uint32_t smb = smem_u32(smf);
    const uint32_t ONESH = 0x3C003C00u;

    const int tid = threadIdx.x, lane = tid & 31, w = tid >> 5;
    const int hh = w & 3, rh = w >> 2;
    const int m0 = ((int)gridDim.x - 1 - (int)blockIdx.x) * 64;   // heavy first
    const int hg = blockIdx.y, b = blockIdx.z;
    const int head = hg * 4 + hh;

    const int arow = ((lane >> 3) & 1) * 8 + (lane & 7);
    const int lrow = ((lane >> 1) & 8) + (lane & 7);
    const int chA  = (lane >> 4) & 1;
    const int chK  = (lane >> 3) & 1;

    // ---- Q staging: 4 heads x 64 rows x 64 dims (2048 octs) ----
#pragma unroll
    for (int t = 0; t < 8; t++) {
        int ol = tid + t * 256;
        int hq = ol >> 9, rem = ol & 511;
        int r = rem >> 3, o = rem & 7;
        uint4 v = ((const uint4*)Qhi)[(size_t)(b * N_ + m0 + r) * (D_ / 8) +
                                      (hg * 4 + hq) * 8 + o];
        *(uint4*)(smf + hq * 8192 + swz(r, o)) = v;
    }
    __syncthreads();

    uint32_t qh[2][4][4];
#pragma unroll
    for (int mi = 0; mi < 2; mi++)
#pragma unroll
        for (int kf = 0; kf < 4; kf++) {
            int r = rh * 32 + mi * 16 + arow;
            LDM4(qh[mi][kf], smb + (uint32_t)(hh * 8192 + r * 128 +
                             (((kf * 2 + chA) ^ (r & 7)) << 4)));
        }
    __syncthreads();

    auto issue_kv = [&](int s, int kt) {
        const uint32_t base = smb + (uint32_t)(s * 16384);
#pragma unroll
        for (int t = 0; t < 2; t++) {
            int ol = tid + t * 256;
            int r = ol >> 3, o = ol & 7;
            size_t gi = (size_t)(b * N_ + kt * 64 + r) * (DH_ / 8) + o;
            uint32_t doff = swz(r, o);
            CP16(base + doff,        (const uint4*)Khi + gi);
            CP16(base + 8192 + doff, (const uint4*)Vhi + gi);
        }
    };

    int gi1[2], gi2[2], qm1[2], qm2[2];
#pragma unroll
    for (int mi = 0; mi < 2; mi++) {
        gi1[mi] = m0 + rh * 32 + mi * 16 + (lane >> 2);
        gi2[mi] = gi1[mi] + 8;
        qm1[mi] = mask[b * N_ + gi1[mi]];
        qm2[mi] = mask[b * N_ + gi2[mi]];
    }

    float accO[2][8][4];
#pragma unroll
    for (int mi = 0; mi < 2; mi++)
#pragma unroll
        for (int f = 0; f < 8; f++)
#pragma unroll
            for (int q = 0; q < 4; q++) accO[mi][f][q] = 0.f;
    float accL[2][4] = {{0.f, 0.f, 0.f, 0.f}, {0.f, 0.f, 0.f, 0.f}};

    const int nkt = (m0 >> 6) + 1;
    issue_kv(0, 0); CPCOMMIT();
    if (nkt > 1) issue_kv(1, 1);
    CPCOMMIT();

    for (int kt = 0; kt < nkt; kt++) {
        CPWAIT1();
        __syncthreads();
        if (kt + 2 < nkt) issue_kv((kt + 2) % 3, kt + 2);
        CPCOMMIT();

        const uint32_t bK = smb + (uint32_t)((kt % 3) * 16384);
        const uint32_t bV = bK + 8192;

        // ---- S = Q K^T (log2 domain) ----
        float s[2][8][4];
#pragma unroll
        for (int mi = 0; mi < 2; mi++)
#pragma unroll
            for (int f = 0; f < 8; f++)
#pragma unroll
                for (int q = 0; q < 4; q++) s[mi][f][q] = 0.f;

#pragma unroll
        for (int kf = 0; kf < 4; kf++)
#pragma unroll
            for (int ng = 0; ng < 4; ng++) {
                uint32_t bh[4];
                int r = ng * 16 + lrow;
                LDM4(bh, bK + (uint32_t)(r * 128 +
                         (((kf * 2 + chK) ^ (r & 7)) << 4)));
#pragma unroll
                for (int mi = 0; mi < 2; mi++) {
                    MMA16816(s[mi][ng * 2],     qh[mi][kf], bh[0], bh[1]);
                    MMA16816(s[mi][ng * 2 + 1], qh[mi][kf], bh[2], bh[3]);
                }
            }

        // ---- mask ----
        if (kt == (m0 >> 6) || !qm1[0] || !qm2[0] || !qm1[1] || !qm2[1]) {
#pragma unroll
            for (int mi = 0; mi < 2; mi++)
#pragma unroll
                for (int f = 0; f < 8; f++) {
                    int gj = kt * 64 + f * 8 + 2 * (lane & 3);
                    if (!qm1[mi])                 { s[mi][f][0] = 0.f; s[mi][f][1] = 0.f; }
                    else { if (gj > gi1[mi])        s[mi][f][0] = -1e30f;
                           if (gj + 1 > gi1[mi])    s[mi][f][1] = -1e30f; }
                    if (!qm2[mi])                 { s[mi][f][2] = 0.f; s[mi][f][3] = 0.f; }
                    else { if (gj > gi2[mi])        s[mi][f][2] = -1e30f;
                           if (gj + 1 > gi2[mi])    s[mi][f][3] = -1e30f; }
                }
        }

        // ---- shift-free softmax ----
#pragma unroll
        for (int mi = 0; mi < 2; mi++)
#pragma unroll
            for (int f = 0; f < 8; f++) {
                s[mi][f][0] = ex2f(s[mi][f][0]);
                s[mi][f][1] = ex2f(s[mi][f][1]);
                s[mi][f][2] = ex2f(s[mi][f][2]);
                s[mi][f][3] = ex2f(s[mi][f][3]);
            }

        // ---- O += P V ; L += P @ ones ----
#pragma unroll
        for (int kf = 0; kf < 4; kf++) {
            uint32_t pah[2][4];
#pragma unroll
            for (int mi = 0; mi < 2; mi++) {
                const float* s0 = s[mi][2 * kf];
                const float* s1 = s[mi][2 * kf + 1];
                pah[mi][0] = packh2(s0[0], s0[1]);
                pah[mi][1] = packh2(s0[2], s0[3]);
                pah[mi][2] = packh2(s1[0], s1[1]);
                pah[mi][3] = packh2(s1[2], s1[3]);
                MMA16816(accL[mi], pah[mi], ONESH, ONESH);
            }
#pragma unroll
            for (int dg = 0; dg < 4; dg++) {
                uint32_t vh[4];
                int r = kf * 16 + arow;
                LDM4T(vh, bV + (uint32_t)(r * 128 +
                          (((dg * 2 + chA) ^ (r & 7)) << 4)));
#pragma unroll
                for (int mi = 0; mi < 2; mi++) {
                    MMA16816(accO[mi][dg * 2],     pah[mi], vh[0], vh[1]);
                    MMA16816(accO[mi][dg * 2 + 1], pah[mi], vh[2], vh[3]);
                }
            }
        }
    }

    // ---- epilogue ----
#pragma unroll
    for (int mi = 0; mi < 2; mi++) {
        const float i1 = 1.f / accL[mi][0], i2 = 1.f / accL[mi][2];
#pragma unroll
        for (int f = 0; f < 8; f++) {
            int col = head * DH_ + f * 8 + 2 * (lane & 3);
            size_t x1 = ((size_t)(b * N_ + gi1[mi]) * D_ + col) >> 1;
            size_t x2 = ((size_t)(b * N_ + gi2[mi]) * D_ + col) >> 1;
            AOhi[x1] = packh2(accO[mi][f][0] * i1, accO[mi][f][1] * i1);
            AOhi[x2] = packh2(accO[mi][f][2] * i2, accO[mi][f][3] * i2);
        }
    }
}

// ============================================================================
extern "C" void kernel_launch(void* const* d_in, const int* in_sizes, int n_in,
                              void* d_out, int out_size)
{
    const float* x    = (const float*)d_in[0];
    const int*   mask = (const int*)d_in[1];
    const float* Wq   = (const float*)d_in[2];
    const float* Wk   = (const float*)d_in[3];
    const float* Wv   = (const float*)d_in[4];
    const float* Wfc  = (const float*)d_in[5];
    const float* bfc  = (const float*)d_in[6];
    float*       out  = (float*)d_out;

    uint32_t *Xhi, *Wqhi, *Wkvhi, *Wfhi, *Qhi, *Khi, *Vhi, *AOhi;
    cudaGetSymbolAddress((void**)&Xhi,   g_Xhi);
    cudaGetSymbolAddress((void**)&Wqhi,  g_Wqhi);
    cudaGetSymbolAddress((void**)&Wkvhi, g_Wkvhi);
    cudaGetSymbolAddress((void**)&Wfhi,  g_Wfhi);
    cudaGetSymbolAddress((void**)&Qhi,   g_Qhi);
    cudaGetSymbolAddress((void**)&Khi,   g_Khi);
    cudaGetSymbolAddress((void**)&Vhi,   g_Vhi);
    cudaGetSymbolAddress((void**)&AOhi,  g_AOhi);

    const int SM_GB = 3 * (256 + 128) * 128;   // 147456
    const int SM_FL = 3 * 16384;               // 49152
    cudaFuncSetAttribute((const void*)gemm_big<0>,
                         cudaFuncAttributeMaxDynamicSharedMemorySize, SM_GB);
    cudaFuncSetAttribute((const void*)gemm_big<1>,
                         cudaFuncAttributeMaxDynamicSharedMemorySize, SM_GB);
    cudaFuncSetAttribute((const void*)flash_h,
                         cudaFuncAttributeMaxDynamicSharedMemorySize, SM_FL);

    // 1. split all fp32 inputs -> packed fp16 (Wk/Wv stacked into Wkv)
    split_hi<<<(OTOT + 255) / 256, 256>>>(
        x, Wq, Wk, Wv, Wfc, Xhi, Wqhi, Wkvhi, Wfhi);

    // 2. merged Q/K/V projections: bx 0-7 -> Q (scaled), bx 8 -> K|V
    gemm_big<0><<<dim3(9, M_ / 256), 512, SM_GB>>>(
        Xhi, Wqhi, Wkvhi, nullptr, nullptr, Qhi, Khi, Vhi);

    // 3. flash attention (4 heads/CTA) -> AO fp16
    flash_h<<<dim3(N_ / 64, H_ / 4, B_), 256, SM_FL>>>(
        Qhi, Khi, Vhi, mask, AOhi);

    // 4. out = AO Wfc^T + bfc
    gemm_big<1><<<dim3(D_ / 128, M_ / 256), 512, SM_GB>>>(
        AOhi, Wfhi, nullptr, bfc, out, nullptr, nullptr, nullptr);
}

// round 15
// speedup vs baseline: 1.0034x; 1.0034x over previous
#include <cuda_runtime.h>
#include <cuda_fp16.h>
#include <cstdint>

#define B_  2
#define N_  2048
#define D_  1024
#define H_  16
#define DH_ 64
#define M_  (B_ * N_)
#define QSCALE 0.04508422f   // (1/32) * log2(e)

// ---------------- scratch (packed fp16x2 in uint32) ----------------
__device__ uint32_t g_Xhi  [M_ * D_ / 2];
__device__ uint32_t g_Wqhi [D_ * D_ / 2];
__device__ uint32_t g_Wkvhi[2 * DH_ * D_ / 2];   // rows 0-63 = Wk, 64-127 = Wv
__device__ uint32_t g_Wfhi [D_ * D_ / 2];
__device__ uint32_t g_Qhi  [M_ * D_ / 2];
__device__ uint32_t g_Khi  [M_ * DH_ / 2];
__device__ uint32_t g_Vhi  [M_ * DH_ / 2];
__device__ uint32_t g_AOhi [M_ * D_ / 2];

__device__ __forceinline__ uint32_t smem_u32(const void* p) {
    uint32_t a;
    asm("{ .reg .u64 t; cvta.to.shared.u64 t, %1; cvt.u32.u64 %0, t; }"
        : "=r"(a) : "l"(p));
    return a;
}

__device__ __forceinline__ float ex2f(float t) {
    float r;
    asm("ex2.approx.f32 %0, %1;" : "=f"(r) : "f"(t));
    return r;
}

__device__ __forceinline__ uint32_t packh2(float a, float b) {
    __half2 t = __floats2half2_rn(a, b);
    return *(uint32_t*)&t;
}

#define LDM4(r, addr)                                                         \
    asm volatile("ldmatrix.sync.aligned.m8n8.x4.shared.b16 {%0,%1,%2,%3}, [%4];" \
        : "=r"((r)[0]), "=r"((r)[1]), "=r"((r)[2]), "=r"((r)[3])              \
        : "r"(addr))

#define LDM4T(r, addr)                                                        \
    asm volatile("ldmatrix.sync.aligned.m8n8.x4.trans.shared.b16 {%0,%1,%2,%3}, [%4];" \
        : "=r"((r)[0]), "=r"((r)[1]), "=r"((r)[2]), "=r"((r)[3])              \
        : "r"(addr))

#define MMA16816(d, a, b0, b1)                                                \
    asm volatile("mma.sync.aligned.m16n8k16.row.col.f32.f16.f16.f32 "         \
        "{%0,%1,%2,%3},{%4,%5,%6,%7},{%8,%9},{%0,%1,%2,%3};"                  \
        : "+f"((d)[0]), "+f"((d)[1]), "+f"((d)[2]), "+f"((d)[3])              \
        : "r"((a)[0]), "r"((a)[1]), "r"((a)[2]), "r"((a)[3]),                 \
          "r"(b0), "r"(b1))

#define CP16(dst, src)                                                        \
    asm volatile("cp.async.cg.shared.global [%0], [%1], 16;"                  \
        :: "r"(dst), "l"(src))
#define CPCOMMIT() asm volatile("cp.async.commit_group;" ::: "memory")
#define CPWAIT1()  asm volatile("cp.async.wait_group 1;"  ::: "memory")

// xor-swizzled 128B-row smem offset (row r, 16B-oct o) — conflict-free both ways
__device__ __forceinline__ uint32_t swz(int r, int o) {
    return (uint32_t)(r * 128 + ((o ^ (r & 7)) << 4));
}

// ============================================================================
// split: fp32 -> packed fp16. Segments: X | Wq | Wk->Wkv[0:64] | Wv->Wkv[64:] | Wfc
// ============================================================================
#define OX  (M_ * D_ / 8)
#define OWQ (D_ * D_ / 8)
#define OWK (DH_ * D_ / 8)
#define OTOT (OX + OWQ + 2 * OWK + OWQ)

__global__ __launch_bounds__(256) void split_hi(
    const float* __restrict__ x,  const float* __restrict__ Wq,
    const float* __restrict__ Wk, const float* __restrict__ Wv,
    const float* __restrict__ Wfc,
    uint32_t* __restrict__ Xhi,  uint32_t* __restrict__ Wqhi,
    uint32_t* __restrict__ Wkvhi, uint32_t* __restrict__ Wfhi)
{
    int i = blockIdx.x * 256 + threadIdx.x;
    if (i >= OTOT) return;
    const float* src; uint32_t* hi; int j, dj;
    if (i < OX)                      { j = i;                      src = x;   hi = Xhi;   dj = j; }
    else if (i < OX + OWQ)           { j = i - OX;                 src = Wq;  hi = Wqhi;  dj = j; }
    else if (i < OX + OWQ + OWK)     { j = i - OX - OWQ;           src = Wk;  hi = Wkvhi; dj = j; }
    else if (i < OX + OWQ + 2 * OWK) { j = i - OX - OWQ - OWK;     src = Wv;  hi = Wkvhi; dj = j + OWK; }
    else                             { j = i - OX - OWQ - 2 * OWK; src = Wfc; hi = Wfhi;  dj = j; }
    const float4* s = (const float4*)src + (size_t)j * 2;
    float4 a = s[0], b = s[1];
    uint4 h;
    h.x = packh2(a.x, a.y); h.y = packh2(a.z, a.w);
    h.z = packh2(b.x, b.y); h.w = packh2(b.z, b.w);
    ((uint4*)hi)[dj] = h;
}

// ============================================================================
// Big-tile fp16 GEMM: 256x128 CTA tile, 256 threads (8 warps: 4 wm x 2 wn),
// warp tile 64x64, K-step 64, 3-stage cp.async, xor-swizzled smem,
// EXPLICIT register double-buffering of ldmatrix frags across kb sub-steps.
// EPI 0: QKV (bx<8 -> Qhi cols bx*128, scaled; bx==8 -> K cols 0-63 / V 64-127)
// EPI 1: FC  (fp32 out + bias), B = Wfhi.
// ============================================================================
template <int EPI>
__global__ __launch_bounds__(256) void gemm_big(
    const uint32_t* __restrict__ Ahi, const uint32_t* __restrict__ Bq,
    const uint32_t* __restrict__ Bkv,
    const float* __restrict__ bias, float* __restrict__ C,
    uint32_t* __restrict__ Qhi, uint32_t* __restrict__ Khi,
    uint32_t* __restrict__ Vhi)
{
    extern __shared__ char smc[];
    constexpr int ASZ = 256 * 128, BSZ = 128 * 128, STAGE = ASZ + BSZ;
    const uint32_t smb = smem_u32(smc);

    const int tid = threadIdx.x, lane = tid & 31, warp = tid >> 5;
    const int wm = warp & 3, wn = warp >> 2;            // 4 x 2
    const int m0 = blockIdx.y * 256;
    const int bx = blockIdx.x;

    const uint32_t* Bp;
    if (EPI == 0) Bp = (bx < 8) ? (Bq + (size_t)bx * 128 * (D_ / 2)) : Bkv;
    else          Bp = Bq + (size_t)bx * 128 * (D_ / 2);

    const int arow = ((lane >> 3) & 1) * 8 + (lane & 7);
    const int lrow = ((lane >> 1) & 8) + (lane & 7);
    const int chA  = (lane >> 4) & 1;
    const int chK  = (lane >> 3) & 1;

    float acc[4][8][4];                                  // 128 regs
#pragma unroll
    for (int mi = 0; mi < 4; mi++)
#pragma unroll
        for (int f = 0; f < 8; f++)
#pragma unroll
            for (int q = 0; q < 4; q++) acc[mi][f][q] = 0.f;

    const int K8 = D_ / 8;
    const int nkt = D_ / 64;

    auto load_stage = [&](int s, int it) {
        const uint32_t sb = smb + s * STAGE;
        const int ob = it * 8;
#pragma unroll
        for (int t = 0; t < 8; t++) {          // A: 2048 octs / 256 thr
            int ol = tid + t * 256;
            int r = ol >> 3, o = ol & 7;
            CP16(sb + swz(r, o), (const uint4*)Ahi + (size_t)(m0 + r) * K8 + ob + o);
        }
#pragma unroll
        for (int t = 0; t < 4; t++) {          // B: 1024 octs / 256 thr
            int ol = tid + t * 256;
            int r = ol >> 3, o = ol & 7;
            CP16(sb + ASZ + swz(r, o), (const uint4*)Bp + (size_t)r * K8 + ob + o);
        }
    };

    load_stage(0, 0); CPCOMMIT();
    load_stage(1, 1); CPCOMMIT();

    for (int it = 0; it < nkt; it++) {
        CPWAIT1();
        __syncthreads();
        if (it + 2 < nkt) load_stage((it + 2) % 3, it + 2);
        CPCOMMIT();

        const uint32_t sA = smb + (it % 3) * STAGE;
        const uint32_t sB = sA + ASZ;

        // --- double-buffered fragment pipeline across kb ---
        uint32_t ah[2][4][4], bh[2][4][4];

#pragma unroll
        for (int mi = 0; mi < 4; mi++) {
            int r = wm * 64 + mi * 16 + arow;
            LDM4(ah[0][mi], sA + (uint32_t)(r * 128 + ((chA ^ (r & 7)) << 4)));
        }
#pragma unroll
        for (int j = 0; j < 4; j++) {
            int r = wn * 64 + j * 16 + lrow;
            LDM4(bh[0][j], sB + (uint32_t)(r * 128 + ((chK ^ (r & 7)) << 4)));
        }

#pragma unroll
        for (int kb = 0; kb < 4; kb++) {
            const int cur = kb & 1, nxt = cur ^ 1;
            if (kb < 3) {
#pragma unroll
                for (int mi = 0; mi < 4; mi++) {
                    int r = wm * 64 + mi * 16 + arow;
                    LDM4(ah[nxt][mi], sA + (uint32_t)(r * 128 +
                                 ((((kb + 1) * 2 + chA) ^ (r & 7)) << 4)));
                }
#pragma unroll
                for (int j = 0; j < 4; j++) {
                    int r = wn * 64 + j * 16 + lrow;
                    LDM4(bh[nxt][j], sB + (uint32_t)(r * 128 +
                                 ((((kb + 1) * 2 + chK) ^ (r & 7)) << 4)));
                }
            }
#pragma unroll
            for (int j = 0; j < 4; j++)
#pragma unroll
                for (int mi = 0; mi < 4; mi++) {
                    MMA16816(acc[mi][j * 2],     ah[cur][mi], bh[cur][j][0], bh[cur][j][1]);
                    MMA16816(acc[mi][j * 2 + 1], ah[cur][mi], bh[cur][j][2], bh[cur][j][3]);
                }
        }
    }

    // epilogue
#pragma unroll
    for (int mi = 0; mi < 4; mi++)
#pragma unroll
        for (int f = 0; f < 8; f++) {
            int row = m0 + wm * 64 + mi * 16 + (lane >> 2);
            int lc  = wn * 64 + f * 8 + (lane & 3) * 2;
            float v0 = acc[mi][f][0], v1 = acc[mi][f][1];
            float v2 = acc[mi][f][2], v3 = acc[mi][f][3];
            if (EPI == 0) {
                if (bx < 8) {
                    int col = bx * 128 + lc;
                    Qhi[((size_t)row * D_ + col) >> 1] =
                        packh2(v0 * QSCALE, v1 * QSCALE);
                    Qhi[((size_t)(row + 8) * D_ + col) >> 1] =
                        packh2(v2 * QSCALE, v3 * QSCALE);
                } else if (lc < 64) {
                    Khi[((size_t)row * DH_ + lc) >> 1]       = packh2(v0, v1);
                    Khi[((size_t)(row + 8) * DH_ + lc) >> 1] = packh2(v2, v3);
                } else {
                    Vhi[((size_t)row * DH_ + lc - 64) >> 1]       = packh2(v0, v1);
                    Vhi[((size_t)(row + 8) * DH_ + lc - 64) >> 1] = packh2(v2, v3);
                }
            } else {
                int col = bx * 128 + lc;
                float b0 = bias[col], b1 = bias[col + 1];
                *(float2*)&C[(size_t)row * D_ + col] =
                    make_float2(v0 + b0, v1 + b1);
                *(float2*)&C[(size_t)(row + 8) * D_ + col] =
                    make_float2(v2 + b0, v3 + b1);
            }
        }
}

// ============================================================================
// Flash attention: CTA = 64 q-rows x 4 heads (K/V loaded ONCE per CTA for all
// 4 heads). 256 threads, 8 warps: warp = 32 rows of head (warp&3), half (warp>>2).
// Shift-free softmax, tensor-pipe row sums, 3-stage cp.async. (unchanged)
// ============================================================================
__global__ __launch_bounds__(256) void flash_h(
    const uint32_t* __restrict__ Qhi, const uint32_t* __restrict__ Khi,
    const uint32_t* __restrict__ Vhi, const int* __restrict__ mask,
    uint32_t* __restrict__ AOhi)
{
    extern __shared__ char smf[];
    const uint32_t smb = smem_u32(smf);
    const uint32_t ONESH = 0x3C003C00u;

    const int tid = threadIdx.x, lane = tid & 31, w = tid >> 5;
    const int hh = w & 3, rh = w >> 2;
    const int m0 = ((int)gridDim.x - 1 - (int)blockIdx.x) * 64;   // heavy first
    const int hg = blockIdx.y, b = blockIdx.z;
    const int head = hg * 4 + hh;

    const int arow = ((lane >> 3) & 1) * 8 + (lane & 7);
    const int lrow = ((lane >> 1) & 8) + (lane & 7);
    const int chA  = (lane >> 4) & 1;
    const int chK  = (lane >> 3) & 1;

    // ---- Q staging: 4 heads x 64 rows x 64 dims (2048 octs) ----
#pragma unroll
    for (int t = 0; t < 8; t++) {
        int ol = tid + t * 256;
        int hq = ol >> 9, rem = ol & 511;
        int r = rem >> 3, o = rem & 7;
        uint4 v = ((const uint4*)Qhi)[(size_t)(b * N_ + m0 + r) * (D_ / 8) +
                                      (hg * 4 + hq) * 8 + o];
        *(uint4*)(smf + hq * 8192 + swz(r, o)) = v;
    }
    __syncthreads();

    uint32_t qh[2][4][4];
#pragma unroll
    for (int mi = 0; mi < 2; mi++)
#pragma unroll
        for (int kf = 0; kf < 4; kf++) {
            int r = rh * 32 + mi * 16 + arow;
            LDM4(qh[mi][kf], smb + (uint32_t)(hh * 8192 + r * 128 +
                             (((kf * 2 + chA) ^ (r & 7)) << 4)));
        }
    __syncthreads();

    auto issue_kv = [&](int s, int kt) {
        const uint32_t base = smb + (uint32_t)(s * 16384);
#pragma unroll
        for (int t = 0; t < 2; t++) {
            int ol = tid + t * 256;
            int r = ol >> 3, o = ol & 7;
            size_t gi = (size_t)(b * N_ + kt * 64 + r) * (DH_ / 8) + o;
            uint32_t doff = swz(r, o);
            CP16(base + doff,        (const uint4*)Khi + gi);
            CP16(base + 8192 + doff, (const uint4*)Vhi + gi);
        }
    };

    int gi1[2], gi2[2], qm1[2], qm2[2];
#pragma unroll
    for (int mi = 0; mi < 2; mi++) {
        gi1[mi] = m0 + rh * 32 + mi * 16 + (lane >> 2);
        gi2[mi] = gi1[mi] + 8;
        qm1[mi] = mask[b * N_ + gi1[mi]];
        qm2[mi] = mask[b * N_ + gi2[mi]];
    }

    float accO[2][8][4];
#pragma unroll
    for (int mi = 0; mi < 2; mi++)
#pragma unroll
        for (int f = 0; f < 8; f++)
#pragma unroll
            for (int q = 0; q < 4; q++) accO[mi][f][q] = 0.f;
    float accL[2][4] = {{0.f, 0.f, 0.f, 0.f}, {0.f, 0.f, 0.f, 0.f}};

    const int nkt = (m0 >> 6) + 1;
    issue_kv(0, 0); CPCOMMIT();
    if (nkt > 1) issue_kv(1, 1);
    CPCOMMIT();

    for (int kt = 0; kt < nkt; kt++) {
        CPWAIT1();
        __syncthreads();
        if (kt + 2 < nkt) issue_kv((kt + 2) % 3, kt + 2);
        CPCOMMIT();

        const uint32_t bK = smb + (uint32_t)((kt % 3) * 16384);
        const uint32_t bV = bK + 8192;

        // ---- S = Q K^T (log2 domain) ----
        float s[2][8][4];
#pragma unroll
        for (int mi = 0; mi < 2; mi++)
#pragma unroll
            for (int f = 0; f < 8; f++)
#pragma unroll
                for (int q = 0; q < 4; q++) s[mi][f][q] = 0.f;

#pragma unroll
        for (int kf = 0; kf < 4; kf++)
#pragma unroll
            for (int ng = 0; ng < 4; ng++) {
                uint32_t bh[4];
                int r = ng * 16 + lrow;
                LDM4(bh, bK + (uint32_t)(r * 128 +
                         (((kf * 2 + chK) ^ (r & 7)) << 4)));
#pragma unroll
                for (int mi = 0; mi < 2; mi++) {
                    MMA16816(s[mi][ng * 2],     qh[mi][kf], bh[0], bh[1]);
                    MMA16816(s[mi][ng * 2 + 1], qh[mi][kf], bh[2], bh[3]);
                }
            }

        // ---- mask ----
        if (kt == (m0 >> 6) || !qm1[0] || !qm2[0] || !qm1[1] || !qm2[1]) {
#pragma unroll
            for (int mi = 0; mi < 2; mi++)
#pragma unroll
                for (int f = 0; f < 8; f++) {
                    int gj = kt * 64 + f * 8 + 2 * (lane & 3);
                    if (!qm1[mi])                 { s[mi][f][0] = 0.f; s[mi][f][1] = 0.f; }
                    else { if (gj > gi1[mi])        s[mi][f][0] = -1e30f;
                           if (gj + 1 > gi1[mi])    s[mi][f][1] = -1e30f; }
                    if (!qm2[mi])                 { s[mi][f][2] = 0.f; s[mi][f][3] = 0.f; }
                    else { if (gj > gi2[mi])        s[mi][f][2] = -1e30f;
                           if (gj + 1 > gi2[mi])    s[mi][f][3] = -1e30f; }
                }
        }

        // ---- shift-free softmax ----
#pragma unroll
        for (int mi = 0; mi < 2; mi++)
#pragma unroll
            for (int f = 0; f < 8; f++) {
                s[mi][f][0] = ex2f(s[mi][f][0]);
                s[mi][f][1] = ex2f(s[mi][f][1]);
                s[mi][f][2] = ex2f(s[mi][f][2]);
                s[mi][f][3] = ex2f(s[mi][f][3]);
            }

        // ---- O += P V ; L += P @ ones ----
#pragma unroll
        for (int kf = 0; kf < 4; kf++) {
            uint32_t pah[2][4];
#pragma unroll
            for (int mi = 0; mi < 2; mi++) {
                const float* s0 = s[mi][2 * kf];
                const float* s1 = s[mi][2 * kf + 1];
                pah[mi][0] = packh2(s0[0], s0[1]);
                pah[mi][1] = packh2(s0[2], s0[3]);
                pah[mi][2] = packh2(s1[0], s1[1]);
                pah[mi][3] = packh2(s1[2], s1[3]);
                MMA16816(accL[mi], pah[mi], ONESH, ONESH);
            }
#pragma unroll
            for (int dg = 0; dg < 4; dg++) {
                uint32_t vh[4];
                int r = kf * 16 + arow;
                LDM4T(vh, bV + (uint32_t)(r * 128 +
                          (((dg * 2 + chA) ^ (r & 7)) << 4)));
#pragma unroll
                for (int mi = 0; mi < 2; mi++) {
                    MMA16816(accO[mi][dg * 2],     pah[mi], vh[0], vh[1]);
                    MMA16816(accO[mi][dg * 2 + 1], pah[mi], vh[2], vh[3]);
                }
            }
        }
    }

    // ---- epilogue ----
#pragma unroll
    for (int mi = 0; mi < 2; mi++) {
        const float i1 = 1.f / accL[mi][0], i2 = 1.f / accL[mi][2];
#pragma unroll
        for (int f = 0; f < 8; f++) {
            int col = head * DH_ + f * 8 + 2 * (lane & 3);
            size_t x1 = ((size_t)(b * N_ + gi1[mi]) * D_ + col) >> 1;
            size_t x2 = ((size_t)(b * N_ + gi2[mi]) * D_ + col) >> 1;
            AOhi[x1] = packh2(accO[mi][f][0] * i1, accO[mi][f][1] * i1);
            AOhi[x2] = packh2(accO[mi][f][2] * i2, accO[mi][f][3] * i2);
        }
    }
}

// ============================================================================
extern "C" void kernel_launch(void* const* d_in, const int* in_sizes, int n_in,
                              void* d_out, int out_size)
{
    const float* x    = (const float*)d_in[0];
    const int*   mask = (const int*)d_in[1];
    const float* Wq   = (const float*)d_in[2];
    const float* Wk   = (const float*)d_in[3];
    const float* Wv   = (const float*)d_in[4];
    const float* Wfc  = (const float*)d_in[5];
    const float* bfc  = (const float*)d_in[6];
    float*       out  = (float*)d_out;

    uint32_t *Xhi, *Wqhi, *Wkvhi, *Wfhi, *Qhi, *Khi, *Vhi, *AOhi;
    cudaGetSymbolAddress((void**)&Xhi,   g_Xhi);
    cudaGetSymbolAddress((void**)&Wqhi,  g_Wqhi);
    cudaGetSymbolAddress((void**)&Wkvhi, g_Wkvhi);
    cudaGetSymbolAddress((void**)&Wfhi,  g_Wfhi);
    cudaGetSymbolAddress((void**)&Qhi,   g_Qhi);
    cudaGetSymbolAddress((void**)&Khi,   g_Khi);
    cudaGetSymbolAddress((void**)&Vhi,   g_Vhi);
    cudaGetSymbolAddress((void**)&AOhi,  g_AOhi);

    const int SM_GB = 3 * (256 + 128) * 128;   // 147456
    const int SM_FL = 3 * 16384;               // 49152
    cudaFuncSetAttribute((const void*)gemm_big<0>,
                         cudaFuncAttributeMaxDynamicSharedMemorySize, SM_GB);
    cudaFuncSetAttribute((const void*)gemm_big<1>,
                         cudaFuncAttributeMaxDynamicSharedMemorySize, SM_GB);
    cudaFuncSetAttribute((const void*)flash_h,
                         cudaFuncAttributeMaxDynamicSharedMemorySize, SM_FL);

    // 1. split all fp32 inputs -> packed fp16 (Wk/Wv stacked into Wkv)
    split_hi<<<(OTOT + 255) / 256, 256>>>(
        x, Wq, Wk, Wv, Wfc, Xhi, Wqhi, Wkvhi, Wfhi);

    // 2. merged Q/K/V projections: bx 0-7 -> Q (scaled), bx 8 -> K|V
    gemm_big<0><<<dim3(9, M_ / 256), 256, SM_GB>>>(
        Xhi, Wqhi, Wkvhi, nullptr, nullptr, Qhi, Khi, Vhi);

    // 3. flash attention (4 heads/CTA) -> AO fp16
    flash_h<<<dim3(N_ / 64, H_ / 4, B_), 256, SM_FL>>>(
        Qhi, Khi, Vhi, mask, AOhi);

    // 4. out = AO Wfc^T + bfc
    gemm_big<1><<<dim3(D_ / 128, M_ / 256), 256, SM_GB>>>(
        AOhi, Wfhi, nullptr, bfc, out, nullptr, nullptr, nullptr);
}

// round 16
// speedup vs baseline: 1.0146x; 1.0111x over previous
#include <cuda_runtime.h>
#include <cuda_fp16.h>
#include <cstdint>

#define B_  2
#define N_  2048
#define D_  1024
#define H_  16
#define DH_ 64
#define M_  (B_ * N_)
#define QSCALE 0.04508422f   // (1/32) * log2(e)

// ---------------- scratch (packed fp16x2 in uint32) ----------------
__device__ uint32_t g_Xhi  [M_ * D_ / 2];
__device__ uint32_t g_Wqhi [D_ * D_ / 2];
__device__ uint32_t g_Wkvhi[2 * DH_ * D_ / 2];   // rows 0-63 = Wk, 64-127 = Wv
__device__ uint32_t g_Wfhi [D_ * D_ / 2];
__device__ uint32_t g_Qhi  [M_ * D_ / 2];
__device__ uint32_t g_Khi  [M_ * DH_ / 2];
__device__ uint32_t g_Vhi  [M_ * DH_ / 2];
__device__ uint32_t g_AOhi [M_ * D_ / 2];

__device__ __forceinline__ uint32_t smem_u32(const void* p) {
    uint32_t a;
    asm("{ .reg .u64 t; cvta.to.shared.u64 t, %1; cvt.u32.u64 %0, t; }"
        : "=r"(a) : "l"(p));
    return a;
}

__device__ __forceinline__ float ex2f(float t) {
    float r;
    asm("ex2.approx.f32 %0, %1;" : "=f"(r) : "f"(t));
    return r;
}

__device__ __forceinline__ uint32_t packh2(float a, float b) {
    __half2 t = __floats2half2_rn(a, b);
    return *(uint32_t*)&t;
}

#define LDM4(r, addr)                                                         \
    asm volatile("ldmatrix.sync.aligned.m8n8.x4.shared.b16 {%0,%1,%2,%3}, [%4];" \
        : "=r"((r)[0]), "=r"((r)[1]), "=r"((r)[2]), "=r"((r)[3])              \
        : "r"(addr))

#define LDM4T(r, addr)                                                        \
    asm volatile("ldmatrix.sync.aligned.m8n8.x4.trans.shared.b16 {%0,%1,%2,%3}, [%4];" \
        : "=r"((r)[0]), "=r"((r)[1]), "=r"((r)[2]), "=r"((r)[3])              \
        : "r"(addr))

#define MMA16816(d, a, b0, b1)                                                \
    asm volatile("mma.sync.aligned.m16n8k16.row.col.f32.f16.f16.f32 "         \
        "{%0,%1,%2,%3},{%4,%5,%6,%7},{%8,%9},{%0,%1,%2,%3};"                  \
        : "+f"((d)[0]), "+f"((d)[1]), "+f"((d)[2]), "+f"((d)[3])              \
        : "r"((a)[0]), "r"((a)[1]), "r"((a)[2]), "r"((a)[3]),                 \
          "r"(b0), "r"(b1))

#define CP16(dst, src)                                                        \
    asm volatile("cp.async.cg.shared.global [%0], [%1], 16;"                  \
        :: "r"(dst), "l"(src))
#define CPCOMMIT() asm volatile("cp.async.commit_group;" ::: "memory")
#define CPWAIT1()  asm volatile("cp.async.wait_group 1;"  ::: "memory")

// xor-swizzled 128B-row smem offset (row r, 16B-oct o) — conflict-free both ways
__device__ __forceinline__ uint32_t swz(int r, int o) {
    return (uint32_t)(r * 128 + ((o ^ (r & 7)) << 4));
}

// ============================================================================
// split: fp32 -> packed fp16. Segments: X | Wq | Wk->Wkv[0:64] | Wv->Wkv[64:] | Wfc
// ============================================================================
#define OX  (M_ * D_ / 8)
#define OWQ (D_ * D_ / 8)
#define OWK (DH_ * D_ / 8)
#define OTOT (OX + OWQ + 2 * OWK + OWQ)

__global__ __launch_bounds__(256) void split_hi(
    const float* __restrict__ x,  const float* __restrict__ Wq,
    const float* __restrict__ Wk, const float* __restrict__ Wv,
    const float* __restrict__ Wfc,
    uint32_t* __restrict__ Xhi,  uint32_t* __restrict__ Wqhi,
    uint32_t* __restrict__ Wkvhi, uint32_t* __restrict__ Wfhi)
{
    int i = blockIdx.x * 256 + threadIdx.x;
    if (i >= OTOT) return;
    const float* src; uint32_t* hi; int j, dj;
    if (i < OX)                      { j = i;                      src = x;   hi = Xhi;   dj = j; }
    else if (i < OX + OWQ)           { j = i - OX;                 src = Wq;  hi = Wqhi;  dj = j; }
    else if (i < OX + OWQ + OWK)     { j = i - OX - OWQ;           src = Wk;  hi = Wkvhi; dj = j; }
    else if (i < OX + OWQ + 2 * OWK) { j = i - OX - OWQ - OWK;     src = Wv;  hi = Wkvhi; dj = j + OWK; }
    else                             { j = i - OX - OWQ - 2 * OWK; src = Wfc; hi = Wfhi;  dj = j; }
    const float4* s = (const float4*)src + (size_t)j * 2;
    float4 a = s[0], b = s[1];
    uint4 h;
    h.x = packh2(a.x, a.y); h.y = packh2(a.z, a.w);
    h.z = packh2(b.x, b.y); h.w = packh2(b.z, b.w);
    ((uint4*)hi)[dj] = h;
}

// ============================================================================
// fp16 GEMM: 128x128 CTA tile, 256 threads (8 warps: 4 wm x 2 wn),
// warp tile 32x64, K-step 64, 3-stage cp.async (32KB/stage -> 2 CTAs/SM).
// EPI 0: QKV (bx<8 -> Qhi cols bx*128, scaled; bx==8 -> K cols 0-63 / V 64-127)
// EPI 1: FC  (fp32 out + bias), B = Wfhi.
// ============================================================================
template <int EPI>
__global__ __launch_bounds__(256, 2) void gemm_big(
    const uint32_t* __restrict__ Ahi, const uint32_t* __restrict__ Bq,
    const uint32_t* __restrict__ Bkv,
    const float* __restrict__ bias, float* __restrict__ C,
    uint32_t* __restrict__ Qhi, uint32_t* __restrict__ Khi,
    uint32_t* __restrict__ Vhi)
{
    extern __shared__ char smc[];
    constexpr int ASZ = 128 * 128, BSZ = 128 * 128, STAGE = ASZ + BSZ;
    const uint32_t smb = smem_u32(smc);

    const int tid = threadIdx.x, lane = tid & 31, warp = tid >> 5;
    const int wm = warp & 3, wn = warp >> 2;            // 4 x 2
    const int m0 = blockIdx.y * 128;
    const int bx = blockIdx.x;

    const uint32_t* Bp;
    if (EPI == 0) Bp = (bx < 8) ? (Bq + (size_t)bx * 128 * (D_ / 2)) : Bkv;
    else          Bp = Bq + (size_t)bx * 128 * (D_ / 2);

    const int arow = ((lane >> 3) & 1) * 8 + (lane & 7);
    const int lrow = ((lane >> 1) & 8) + (lane & 7);
    const int chA  = (lane >> 4) & 1;
    const int chK  = (lane >> 3) & 1;

    float acc[2][8][4];                                  // 64 regs
#pragma unroll
    for (int mi = 0; mi < 2; mi++)
#pragma unroll
        for (int f = 0; f < 8; f++)
#pragma unroll
            for (int q = 0; q < 4; q++) acc[mi][f][q] = 0.f;

    const int K8 = D_ / 8;
    const int nkt = D_ / 64;

    auto load_stage = [&](int s, int it) {
        const uint32_t sb = smb + s * STAGE;
        const int ob = it * 8;
#pragma unroll
        for (int t = 0; t < 4; t++) {          // A: 1024 octs / 256 thr
            int ol = tid + t * 256;
            int r = ol >> 3, o = ol & 7;
            CP16(sb + swz(r, o), (const uint4*)Ahi + (size_t)(m0 + r) * K8 + ob + o);
        }
#pragma unroll
        for (int t = 0; t < 4; t++) {          // B: 1024 octs / 256 thr
            int ol = tid + t * 256;
            int r = ol >> 3, o = ol & 7;
            CP16(sb + ASZ + swz(r, o), (const uint4*)Bp + (size_t)r * K8 + ob + o);
        }
    };

    load_stage(0, 0); CPCOMMIT();
    load_stage(1, 1); CPCOMMIT();

    for (int it = 0; it < nkt; it++) {
        CPWAIT1();
        __syncthreads();
        if (it + 2 < nkt) load_stage((it + 2) % 3, it + 2);
        CPCOMMIT();

        const uint32_t sA = smb + (it % 3) * STAGE;
        const uint32_t sB = sA + ASZ;

#pragma unroll
        for (int kb = 0; kb < 4; kb++) {
            uint32_t ah[2][4];
#pragma unroll
            for (int mi = 0; mi < 2; mi++) {
                int r = wm * 32 + mi * 16 + arow;
                LDM4(ah[mi], sA + (uint32_t)(r * 128 +
                             (((kb * 2 + chA) ^ (r & 7)) << 4)));
            }
#pragma unroll
            for (int j = 0; j < 4; j++) {
                uint32_t bh[4];
                int brow = wn * 64 + j * 16 + lrow;
                LDM4(bh, sB + (uint32_t)(brow * 128 +
                         (((kb * 2 + chK) ^ (brow & 7)) << 4)));
#pragma unroll
                for (int mi = 0; mi < 2; mi++) {
                    MMA16816(acc[mi][j * 2],     ah[mi], bh[0], bh[1]);
                    MMA16816(acc[mi][j * 2 + 1], ah[mi], bh[2], bh[3]);
                }
            }
        }
    }

    // epilogue
#pragma unroll
    for (int mi = 0; mi < 2; mi++)
#pragma unroll
        for (int f = 0; f < 8; f++) {
            int row = m0 + wm * 32 + mi * 16 + (lane >> 2);
            int lc  = wn * 64 + f * 8 + (lane & 3) * 2;
            float v0 = acc[mi][f][0], v1 = acc[mi][f][1];
            float v2 = acc[mi][f][2], v3 = acc[mi][f][3];
            if (EPI == 0) {
                if (bx < 8) {
                    int col = bx * 128 + lc;
                    Qhi[((size_t)row * D_ + col) >> 1] =
                        packh2(v0 * QSCALE, v1 * QSCALE);
                    Qhi[((size_t)(row + 8) * D_ + col) >> 1] =
                        packh2(v2 * QSCALE, v3 * QSCALE);
                } else if (lc < 64) {
                    Khi[((size_t)row * DH_ + lc) >> 1]       = packh2(v0, v1);
                    Khi[((size_t)(row + 8) * DH_ + lc) >> 1] = packh2(v2, v3);
                } else {
                    Vhi[((size_t)row * DH_ + lc - 64) >> 1]       = packh2(v0, v1);
                    Vhi[((size_t)(row + 8) * DH_ + lc - 64) >> 1] = packh2(v2, v3);
                }
            } else {
                int col = bx * 128 + lc;
                float b0 = bias[col], b1 = bias[col + 1];
                *(float2*)&C[(size_t)row * D_ + col] =
                    make_float2(v0 + b0, v1 + b1);
                *(float2*)&C[(size_t)(row + 8) * D_ + col] =
                    make_float2(v2 + b0, v3 + b1);
            }
        }
}

// ============================================================================
// Flash attention: CTA = 64 q-rows x 4 heads (K/V loaded ONCE per CTA for all
// 4 heads). 256 threads, 8 warps: warp = 32 rows of head (warp&3), half (warp>>2).
// Shift-free softmax, tensor-pipe row sums, 3-stage cp.async. (unchanged)
// ============================================================================
__global__ __launch_bounds__(256) void flash_h(
    const uint32_t* __restrict__ Qhi, const uint32_t* __restrict__ Khi,
    const uint32_t* __restrict__ Vhi, const int* __restrict__ mask,
    uint32_t* __restrict__ AOhi)
{
    extern __shared__ char smf[];
    const uint32_t smb = smem_u32(smf);
    const uint32_t ONESH = 0x3C003C00u;

    const int tid = threadIdx.x, lane = tid & 31, w = tid >> 5;
    const int hh = w & 3, rh = w >> 2;
    const int m0 = ((int)gridDim.x - 1 - (int)blockIdx.x) * 64;   // heavy first
    const int hg = blockIdx.y, b = blockIdx.z;
    const int head = hg * 4 + hh;

    const int arow = ((lane >> 3) & 1) * 8 + (lane & 7);
    const int lrow = ((lane >> 1) & 8) + (lane & 7);
    const int chA  = (lane >> 4) & 1;
    const int chK  = (lane >> 3) & 1;

    // ---- Q staging: 4 heads x 64 rows x 64 dims (2048 octs) ----
#pragma unroll
    for (int t = 0; t < 8; t++) {
        int ol = tid + t * 256;
        int hq = ol >> 9, rem = ol & 511;
        int r = rem >> 3, o = rem & 7;
        uint4 v = ((const uint4*)Qhi)[(size_t)(b * N_ + m0 + r) * (D_ / 8) +
                                      (hg * 4 + hq) * 8 + o];
        *(uint4*)(smf + hq * 8192 + swz(r, o)) = v;
    }
    __syncthreads();

    uint32_t qh[2][4][4];
#pragma unroll
    for (int mi = 0; mi < 2; mi++)
#pragma unroll
        for (int kf = 0; kf < 4; kf++) {
            int r = rh * 32 + mi * 16 + arow;
            LDM4(qh[mi][kf], smb + (uint32_t)(hh * 8192 + r * 128 +
                             (((kf * 2 + chA) ^ (r & 7)) << 4)));
        }
    __syncthreads();

    auto issue_kv = [&](int s, int kt) {
        const uint32_t base = smb + (uint32_t)(s * 16384);
#pragma unroll
        for (int t = 0; t < 2; t++) {
            int ol = tid + t * 256;
            int r = ol >> 3, o = ol & 7;
            size_t gi = (size_t)(b * N_ + kt * 64 + r) * (DH_ / 8) + o;
            uint32_t doff = swz(r, o);
            CP16(base + doff,        (const uint4*)Khi + gi);
            CP16(base + 8192 + doff, (const uint4*)Vhi + gi);
        }
    };

    int gi1[2], gi2[2], qm1[2], qm2[2];
#pragma unroll
    for (int mi = 0; mi < 2; mi++) {
        gi1[mi] = m0 + rh * 32 + mi * 16 + (lane >> 2);
        gi2[mi] = gi1[mi] + 8;
        qm1[mi] = mask[b * N_ + gi1[mi]];
        qm2[mi] = mask[b * N_ + gi2[mi]];
    }

    float accO[2][8][4];
#pragma unroll
    for (int mi = 0; mi < 2; mi++)
#pragma unroll
        for (int f = 0; f < 8; f++)
#pragma unroll
            for (int q = 0; q < 4; q++) accO[mi][f][q] = 0.f;
    float accL[2][4] = {{0.f, 0.f, 0.f, 0.f}, {0.f, 0.f, 0.f, 0.f}};

    const int nkt = (m0 >> 6) + 1;
    issue_kv(0, 0); CPCOMMIT();
    if (nkt > 1) issue_kv(1, 1);
    CPCOMMIT();

    for (int kt = 0; kt < nkt; kt++) {
        CPWAIT1();
        __syncthreads();
        if (kt + 2 < nkt) issue_kv((kt + 2) % 3, kt + 2);
        CPCOMMIT();

        const uint32_t bK = smb + (uint32_t)((kt % 3) * 16384);
        const uint32_t bV = bK + 8192;

        // ---- S = Q K^T (log2 domain) ----
        float s[2][8][4];
#pragma unroll
        for (int mi = 0; mi < 2; mi++)
#pragma unroll
            for (int f = 0; f < 8; f++)
#pragma unroll
                for (int q = 0; q < 4; q++) s[mi][f][q] = 0.f;

#pragma unroll
        for (int kf = 0; kf < 4; kf++)
#pragma unroll
            for (int ng = 0; ng < 4; ng++) {
                uint32_t bh[4];
                int r = ng * 16 + lrow;
                LDM4(bh, bK + (uint32_t)(r * 128 +
                         (((kf * 2 + chK) ^ (r & 7)) << 4)));
#pragma unroll
                for (int mi = 0; mi < 2; mi++) {
                    MMA16816(s[mi][ng * 2],     qh[mi][kf], bh[0], bh[1]);
                    MMA16816(s[mi][ng * 2 + 1], qh[mi][kf], bh[2], bh[3]);
                }
            }

        // ---- mask ----
        if (kt == (m0 >> 6) || !qm1[0] || !qm2[0] || !qm1[1] || !qm2[1]) {
#pragma unroll
            for (int mi = 0; mi < 2; mi++)
#pragma unroll
                for (int f = 0; f < 8; f++) {
                    int gj = kt * 64 + f * 8 + 2 * (lane & 3);
                    if (!qm1[mi])                 { s[mi][f][0] = 0.f; s[mi][f][1] = 0.f; }
                    else { if (gj > gi1[mi])        s[mi][f][0] = -1e30f;
                           if (gj + 1 > gi1[mi])    s[mi][f][1] = -1e30f; }
                    if (!qm2[mi])                 { s[mi][f][2] = 0.f; s[mi][f][3] = 0.f; }
                    else { if (gj > gi2[mi])        s[mi][f][2] = -1e30f;
                           if (gj + 1 > gi2[mi])    s[mi][f][3] = -1e30f; }
                }
        }

        // ---- shift-free softmax ----
#pragma unroll
        for (int mi = 0; mi < 2; mi++)
#pragma unroll
            for (int f = 0; f < 8; f++) {
                s[mi][f][0] = ex2f(s[mi][f][0]);
                s[mi][f][1] = ex2f(s[mi][f][1]);
                s[mi][f][2] = ex2f(s[mi][f][2]);
                s[mi][f][3] = ex2f(s[mi][f][3]);
            }

        // ---- O += P V ; L += P @ ones ----
#pragma unroll
        for (int kf = 0; kf < 4; kf++) {
            uint32_t pah[2][4];
#pragma unroll
            for (int mi = 0; mi < 2; mi++) {
                const float* s0 = s[mi][2 * kf];
                const float* s1 = s[mi][2 * kf + 1];
                pah[mi][0] = packh2(s0[0], s0[1]);
                pah[mi][1] = packh2(s0[2], s0[3]);
                pah[mi][2] = packh2(s1[0], s1[1]);
                pah[mi][3] = packh2(s1[2], s1[3]);
                MMA16816(accL[mi], pah[mi], ONESH, ONESH);
            }
#pragma unroll
            for (int dg = 0; dg < 4; dg++) {
                uint32_t vh[4];
                int r = kf * 16 + arow;
                LDM4T(vh, bV + (uint32_t)(r * 128 +
                          (((dg * 2 + chA) ^ (r & 7)) << 4)));
#pragma unroll
                for (int mi = 0; mi < 2; mi++) {
                    MMA16816(accO[mi][dg * 2],     pah[mi], vh[0], vh[1]);
                    MMA16816(accO[mi][dg * 2 + 1], pah[mi], vh[2], vh[3]);
                }
            }
        }
    }

    // ---- epilogue ----
#pragma unroll
    for (int mi = 0; mi < 2; mi++) {
        const float i1 = 1.f / accL[mi][0], i2 = 1.f / accL[mi][2];
#pragma unroll
        for (int f = 0; f < 8; f++) {
            int col = head * DH_ + f * 8 + 2 * (lane & 3);
            size_t x1 = ((size_t)(b * N_ + gi1[mi]) * D_ + col) >> 1;
            size_t x2 = ((size_t)(b * N_ + gi2[mi]) * D_ + col) >> 1;
            AOhi[x1] = packh2(accO[mi][f][0] * i1, accO[mi][f][1] * i1);
            AOhi[x2] = packh2(accO[mi][f][2] * i2, accO[mi][f][3] * i2);
        }
    }
}

// ============================================================================
extern "C" void kernel_launch(void* const* d_in, const int* in_sizes, int n_in,
                              void* d_out, int out_size)
{
    const float* x    = (const float*)d_in[0];
    const int*   mask = (const int*)d_in[1];
    const float* Wq   = (const float*)d_in[2];
    const float* Wk   = (const float*)d_in[3];
    const float* Wv   = (const float*)d_in[4];
    const float* Wfc  = (const float*)d_in[5];
    const float* bfc  = (const float*)d_in[6];
    float*       out  = (float*)d_out;

    uint32_t *Xhi, *Wqhi, *Wkvhi, *Wfhi, *Qhi, *Khi, *Vhi, *AOhi;
    cudaGetSymbolAddress((void**)&Xhi,   g_Xhi);
    cudaGetSymbolAddress((void**)&Wqhi,  g_Wqhi);
    cudaGetSymbolAddress((void**)&Wkvhi, g_Wkvhi);
    cudaGetSymbolAddress((void**)&Wfhi,  g_Wfhi);
    cudaGetSymbolAddress((void**)&Qhi,   g_Qhi);
    cudaGetSymbolAddress((void**)&Khi,   g_Khi);
    cudaGetSymbolAddress((void**)&Vhi,   g_Vhi);
    cudaGetSymbolAddress((void**)&AOhi,  g_AOhi);

    const int SM_GB = 3 * (128 + 128) * 128;   // 98304 -> 2 CTAs/SM
    const int SM_FL = 3 * 16384;               // 49152
    cudaFuncSetAttribute((const void*)gemm_big<0>,
                         cudaFuncAttributeMaxDynamicSharedMemorySize, SM_GB);
    cudaFuncSetAttribute((const void*)gemm_big<1>,
                         cudaFuncAttributeMaxDynamicSharedMemorySize, SM_GB);
    cudaFuncSetAttribute((const void*)flash_h,
                         cudaFuncAttributeMaxDynamicSharedMemorySize, SM_FL);

    // 1. split all fp32 inputs -> packed fp16 (Wk/Wv stacked into Wkv)
    split_hi<<<(OTOT + 255) / 256, 256>>>(
        x, Wq, Wk, Wv, Wfc, Xhi, Wqhi, Wkvhi, Wfhi);

    // 2. merged Q/K/V projections: bx 0-7 -> Q (scaled), bx 8 -> K|V
    gemm_big<0><<<dim3(9, M_ / 128), 256, SM_GB>>>(
        Xhi, Wqhi, Wkvhi, nullptr, nullptr, Qhi, Khi, Vhi);

    // 3. flash attention (4 heads/CTA) -> AO fp16
    flash_h<<<dim3(N_ / 64, H_ / 4, B_), 256, SM_FL>>>(
        Qhi, Khi, Vhi, mask, AOhi);

    // 4. out = AO Wfc^T + bfc
    gemm_big<1><<<dim3(D_ / 128, M_ / 128), 256, SM_GB>>>(
        AOhi, Wfhi, nullptr, bfc, out, nullptr, nullptr, nullptr);
}

// round 17
// speedup vs baseline: 1.0642x; 1.0489x over previous
#include <cuda_runtime.h>
#include <cuda_fp16.h>
#include <cstdint>

#define B_  2
#define N_  2048
#define D_  1024
#define H_  16
#define DH_ 64
#define M_  (B_ * N_)
#define QSCALE 0.04508422f   // (1/32) * log2(e)

// ---------------- scratch (packed fp16x2 in uint32) ----------------
__device__ uint32_t g_Xhi  [M_ * D_ / 2];
__device__ uint32_t g_Wqhi [D_ * D_ / 2];
__device__ uint32_t g_Wkvhi[2 * DH_ * D_ / 2];   // rows 0-63 = Wk, 64-127 = Wv
__device__ uint32_t g_Wfhi [D_ * D_ / 2];
__device__ uint32_t g_Qhi  [M_ * D_ / 2];
__device__ uint32_t g_Khi  [M_ * DH_ / 2];
__device__ uint32_t g_Vhi  [M_ * DH_ / 2];
__device__ uint32_t g_AOhi [M_ * D_ / 2];

__device__ __forceinline__ uint32_t smem_u32(const void* p) {
    uint32_t a;
    asm("{ .reg .u64 t; cvta.to.shared.u64 t, %1; cvt.u32.u64 %0, t; }"
        : "=r"(a) : "l"(p));
    return a;
}

__device__ __forceinline__ float ex2f(float t) {
    float r;
    asm("ex2.approx.f32 %0, %1;" : "=f"(r) : "f"(t));
    return r;
}

__device__ __forceinline__ uint32_t packh2(float a, float b) {
    __half2 t = __floats2half2_rn(a, b);
    return *(uint32_t*)&t;
}

#define LDM4(r, addr)                                                         \
    asm volatile("ldmatrix.sync.aligned.m8n8.x4.shared.b16 {%0,%1,%2,%3}, [%4];" \
        : "=r"((r)[0]), "=r"((r)[1]), "=r"((r)[2]), "=r"((r)[3])              \
        : "r"(addr))

#define LDM4T(r, addr)                                                        \
    asm volatile("ldmatrix.sync.aligned.m8n8.x4.trans.shared.b16 {%0,%1,%2,%3}, [%4];" \
        : "=r"((r)[0]), "=r"((r)[1]), "=r"((r)[2]), "=r"((r)[3])              \
        : "r"(addr))

#define MMA16816(d, a, b0, b1)                                                \
    asm volatile("mma.sync.aligned.m16n8k16.row.col.f32.f16.f16.f32 "         \
        "{%0,%1,%2,%3},{%4,%5,%6,%7},{%8,%9},{%0,%1,%2,%3};"                  \
        : "+f"((d)[0]), "+f"((d)[1]), "+f"((d)[2]), "+f"((d)[3])              \
        : "r"((a)[0]), "r"((a)[1]), "r"((a)[2]), "r"((a)[3]),                 \
          "r"(b0), "r"(b1))

#define CP16(dst, src)                                                        \
    asm volatile("cp.async.cg.shared.global [%0], [%1], 16;"                  \
        :: "r"(dst), "l"(src))
#define CPCOMMIT() asm volatile("cp.async.commit_group;" ::: "memory")
#define CPWAIT1()  asm volatile("cp.async.wait_group 1;"  ::: "memory")

// xor-swizzled 128B-row smem offset (row r, 16B-oct o)
__device__ __forceinline__ uint32_t swz(int r, int o) {
    return (uint32_t)(r * 128 + ((o ^ (r & 7)) << 4));
}

// ============================================================================
// split: fp32 -> packed fp16. Segments: X | Wq | Wk->Wkv[0:64] | Wv->Wkv[64:] | Wfc
// ============================================================================
#define OX  (M_ * D_ / 8)
#define OWQ (D_ * D_ / 8)
#define OWK (DH_ * D_ / 8)
#define OTOT (OX + OWQ + 2 * OWK + OWQ)

__global__ __launch_bounds__(256) void split_hi(
    const float* __restrict__ x,  const float* __restrict__ Wq,
    const float* __restrict__ Wk, const float* __restrict__ Wv,
    const float* __restrict__ Wfc,
    uint32_t* __restrict__ Xhi,  uint32_t* __restrict__ Wqhi,
    uint32_t* __restrict__ Wkvhi, uint32_t* __restrict__ Wfhi)
{
    int i = blockIdx.x * 256 + threadIdx.x;
    if (i >= OTOT) return;
    const float* src; uint32_t* hi; int j, dj;
    if (i < OX)                      { j = i;                      src = x;   hi = Xhi;   dj = j; }
    else if (i < OX + OWQ)           { j = i - OX;                 src = Wq;  hi = Wqhi;  dj = j; }
    else if (i < OX + OWQ + OWK)     { j = i - OX - OWQ;           src = Wk;  hi = Wkvhi; dj = j; }
    else if (i < OX + OWQ + 2 * OWK) { j = i - OX - OWQ - OWK;     src = Wv;  hi = Wkvhi; dj = j + OWK; }
    else                             { j = i - OX - OWQ - 2 * OWK; src = Wfc; hi = Wfhi;  dj = j; }
    const float4* s = (const float4*)src + (size_t)j * 2;
    float4 a = s[0], b = s[1];
    uint4 h;
    h.x = packh2(a.x, a.y); h.y = packh2(a.z, a.w);
    h.z = packh2(b.x, b.y); h.w = packh2(b.z, b.w);
    ((uint4*)hi)[dj] = h;
}

// ============================================================================
// fp16 GEMM: 128x128 CTA tile, 256 threads (8 warps: 4 wm x 2 wn),
// warp tile 32x64, K-step 64, 3-stage cp.async (32KB/stage -> 2 CTAs/SM).
// EPI 0: QKV; EPI 1: FC (fp32 out + bias).
// ============================================================================
template <int EPI>
__global__ __launch_bounds__(256, 2) void gemm_big(
    const uint32_t* __restrict__ Ahi, const uint32_t* __restrict__ Bq,
    const uint32_t* __restrict__ Bkv,
    const float* __restrict__ bias, float* __restrict__ C,
    uint32_t* __restrict__ Qhi, uint32_t* __restrict__ Khi,
    uint32_t* __restrict__ Vhi)
{
    extern __shared__ char smc[];
    constexpr int ASZ = 128 * 128, BSZ = 128 * 128, STAGE = ASZ + BSZ;
    const uint32_t smb = smem_u32(smc);

    const int tid = threadIdx.x, lane = tid & 31, warp = tid >> 5;
    const int wm = warp & 3, wn = warp >> 2;
    const int m0 = blockIdx.y * 128;
    const int bx = blockIdx.x;

    const uint32_t* Bp;
    if (EPI == 0) Bp = (bx < 8) ? (Bq + (size_t)bx * 128 * (D_ / 2)) : Bkv;
    else          Bp = Bq + (size_t)bx * 128 * (D_ / 2);

    const int arow = ((lane >> 3) & 1) * 8 + (lane & 7);
    const int lrow = ((lane >> 1) & 8) + (lane & 7);
    const int chA  = (lane >> 4) & 1;
    const int chK  = (lane >> 3) & 1;

    float acc[2][8][4];
#pragma unroll
    for (int mi = 0; mi < 2; mi++)
#pragma unroll
        for (int f = 0; f < 8; f++)
#pragma unroll
            for (int q = 0; q < 4; q++) acc[mi][f][q] = 0.f;

    const int K8 = D_ / 8;
    const int nkt = D_ / 64;

    auto load_stage = [&](int s, int it) {
        const uint32_t sb = smb + s * STAGE;
        const int ob = it * 8;
#pragma unroll
        for (int t = 0; t < 4; t++) {
            int ol = tid + t * 256;
            int r = ol >> 3, o = ol & 7;
            CP16(sb + swz(r, o), (const uint4*)Ahi + (size_t)(m0 + r) * K8 + ob + o);
        }
#pragma unroll
        for (int t = 0; t < 4; t++) {
            int ol = tid + t * 256;
            int r = ol >> 3, o = ol & 7;
            CP16(sb + ASZ + swz(r, o), (const uint4*)Bp + (size_t)r * K8 + ob + o);
        }
    };

    load_stage(0, 0); CPCOMMIT();
    load_stage(1, 1); CPCOMMIT();

    for (int it = 0; it < nkt; it++) {
        CPWAIT1();
        __syncthreads();
        if (it + 2 < nkt) load_stage((it + 2) % 3, it + 2);
        CPCOMMIT();

        const uint32_t sA = smb + (it % 3) * STAGE;
        const uint32_t sB = sA + ASZ;

#pragma unroll
        for (int kb = 0; kb < 4; kb++) {
            uint32_t ah[2][4];
#pragma unroll
            for (int mi = 0; mi < 2; mi++) {
                int r = wm * 32 + mi * 16 + arow;
                LDM4(ah[mi], sA + (uint32_t)(r * 128 +
                             (((kb * 2 + chA) ^ (r & 7)) << 4)));
            }
#pragma unroll
            for (int j = 0; j < 4; j++) {
                uint32_t bh[4];
                int brow = wn * 64 + j * 16 + lrow;
                LDM4(bh, sB + (uint32_t)(brow * 128 +
                         (((kb * 2 + chK) ^ (brow & 7)) << 4)));
#pragma unroll
                for (int mi = 0; mi < 2; mi++) {
                    MMA16816(acc[mi][j * 2],     ah[mi], bh[0], bh[1]);
                    MMA16816(acc[mi][j * 2 + 1], ah[mi], bh[2], bh[3]);
                }
            }
        }
    }

#pragma unroll
    for (int mi = 0; mi < 2; mi++)
#pragma unroll
        for (int f = 0; f < 8; f++) {
            int row = m0 + wm * 32 + mi * 16 + (lane >> 2);
            int lc  = wn * 64 + f * 8 + (lane & 3) * 2;
            float v0 = acc[mi][f][0], v1 = acc[mi][f][1];
            float v2 = acc[mi][f][2], v3 = acc[mi][f][3];
            if (EPI == 0) {
                if (bx < 8) {
                    int col = bx * 128 + lc;
                    Qhi[((size_t)row * D_ + col) >> 1] =
                        packh2(v0 * QSCALE, v1 * QSCALE);
                    Qhi[((size_t)(row + 8) * D_ + col) >> 1] =
                        packh2(v2 * QSCALE, v3 * QSCALE);
                } else if (lc < 64) {
                    Khi[((size_t)row * DH_ + lc) >> 1]       = packh2(v0, v1);
                    Khi[((size_t)(row + 8) * DH_ + lc) >> 1] = packh2(v2, v3);
                } else {
                    Vhi[((size_t)row * DH_ + lc - 64) >> 1]       = packh2(v0, v1);
                    Vhi[((size_t)(row + 8) * DH_ + lc - 64) >> 1] = packh2(v2, v3);
                }
            } else {
                int col = bx * 128 + lc;
                float b0 = bias[col], b1 = bias[col + 1];
                *(float2*)&C[(size_t)row * D_ + col] =
                    make_float2(v0 + b0, v1 + b1);
                *(float2*)&C[(size_t)(row + 8) * D_ + col] =
                    make_float2(v2 + b0, v3 + b1);
            }
        }
}

// ============================================================================
// Flash attention: CTA = 32 q-rows x 4 heads, 256 threads (8 warps =
// 4 heads x 2 row-halves of 16). 2 CTAs/SM (regs ~120) -> balanced causal
// schedule + barrier overlap. Shift-free softmax, tensor-pipe row sums,
// 3-stage cp.async K/V pipeline (K/V shared by all 4 heads).
// ============================================================================
__global__ __launch_bounds__(256, 2) void flash_h(
    const uint32_t* __restrict__ Qhi, const uint32_t* __restrict__ Khi,
    const uint32_t* __restrict__ Vhi, const int* __restrict__ mask,
    uint32_t* __restrict__ AOhi)
{
    extern __shared__ char smf[];
    const uint32_t smb = smem_u32(smf);
    const uint32_t ONESH = 0x3C003C00u;

    const int tid = threadIdx.x, lane = tid & 31, w = tid >> 5;
    const int hh = w & 3, rh = w >> 2;
    const int m0 = ((int)gridDim.x - 1 - (int)blockIdx.x) * 32;   // heavy first
    const int hg = blockIdx.y, b = blockIdx.z;
    const int head = hg * 4 + hh;

    const int arow = ((lane >> 3) & 1) * 8 + (lane & 7);
    const int lrow = ((lane >> 1) & 8) + (lane & 7);
    const int chA  = (lane >> 4) & 1;
    const int chK  = (lane >> 3) & 1;

    // ---- Q staging: 4 heads x 32 rows x 64 dims (1024 octs, 16KB) ----
#pragma unroll
    for (int t = 0; t < 4; t++) {
        int ol = tid + t * 256;
        int hq = ol >> 8, rem = ol & 255;
        int r = rem >> 3, o = rem & 7;
        uint4 v = ((const uint4*)Qhi)[(size_t)(b * N_ + m0 + r) * (D_ / 8) +
                                      (hg * 4 + hq) * 8 + o];
        *(uint4*)(smf + hq * 4096 + swz(r, o)) = v;
    }
    __syncthreads();

    uint32_t qh[4][4];
#pragma unroll
    for (int kf = 0; kf < 4; kf++) {
        int r = rh * 16 + arow;
        LDM4(qh[kf], smb + (uint32_t)(hh * 4096 + r * 128 +
                     (((kf * 2 + chA) ^ (r & 7)) << 4)));
    }
    __syncthreads();

    auto issue_kv = [&](int s, int kt) {
        const uint32_t base = smb + (uint32_t)(s * 16384);
#pragma unroll
        for (int t = 0; t < 2; t++) {
            int ol = tid + t * 256;
            int r = ol >> 3, o = ol & 7;
            size_t gi = (size_t)(b * N_ + kt * 64 + r) * (DH_ / 8) + o;
            uint32_t doff = swz(r, o);
            CP16(base + doff,        (const uint4*)Khi + gi);
            CP16(base + 8192 + doff, (const uint4*)Vhi + gi);
        }
    };

    const int gi1 = m0 + rh * 16 + (lane >> 2);
    const int gi2 = gi1 + 8;
    const int qm1 = mask[b * N_ + gi1];
    const int qm2 = mask[b * N_ + gi2];

    float accO[8][4];
#pragma unroll
    for (int f = 0; f < 8; f++)
#pragma unroll
        for (int q = 0; q < 4; q++) accO[f][q] = 0.f;
    float accL[4] = {0.f, 0.f, 0.f, 0.f};

    const int nkt = (m0 >> 6) + 1;     // key tiles 0 .. m0/64
    const int dkt = m0 >> 6;           // diagonal tile
    issue_kv(0, 0); CPCOMMIT();
    if (nkt > 1) issue_kv(1, 1);
    CPCOMMIT();

    for (int kt = 0; kt < nkt; kt++) {
        CPWAIT1();
        __syncthreads();
        if (kt + 2 < nkt) issue_kv((kt + 2) % 3, kt + 2);
        CPCOMMIT();

        const uint32_t bK = smb + (uint32_t)((kt % 3) * 16384);
        const uint32_t bV = bK + 8192;

        // ---- S = Q K^T (log2 domain) ----
        float s[8][4];
#pragma unroll
        for (int f = 0; f < 8; f++)
#pragma unroll
            for (int q = 0; q < 4; q++) s[f][q] = 0.f;

#pragma unroll
        for (int kf = 0; kf < 4; kf++)
#pragma unroll
            for (int ng = 0; ng < 4; ng++) {
                uint32_t bh[4];
                int r = ng * 16 + lrow;
                LDM4(bh, bK + (uint32_t)(r * 128 +
                         (((kf * 2 + chK) ^ (r & 7)) << 4)));
                MMA16816(s[ng * 2],     qh[kf], bh[0], bh[1]);
                MMA16816(s[ng * 2 + 1], qh[kf], bh[2], bh[3]);
            }

        // ---- mask ----
        if (kt == dkt || !qm1 || !qm2) {
#pragma unroll
            for (int f = 0; f < 8; f++) {
                int gj = kt * 64 + f * 8 + 2 * (lane & 3);
                if (!qm1)              { s[f][0] = 0.f; s[f][1] = 0.f; }
                else { if (gj > gi1)     s[f][0] = -1e30f;
                       if (gj + 1 > gi1) s[f][1] = -1e30f; }
                if (!qm2)              { s[f][2] = 0.f; s[f][3] = 0.f; }
                else { if (gj > gi2)     s[f][2] = -1e30f;
                       if (gj + 1 > gi2) s[f][3] = -1e30f; }
            }
        }

        // ---- shift-free softmax ----
#pragma unroll
        for (int f = 0; f < 8; f++) {
            s[f][0] = ex2f(s[f][0]);
            s[f][1] = ex2f(s[f][1]);
            s[f][2] = ex2f(s[f][2]);
            s[f][3] = ex2f(s[f][3]);
        }

        // ---- O += P V ; L += P @ ones ----
#pragma unroll
        for (int kf = 0; kf < 4; kf++) {
            const float* s0 = s[2 * kf];
            const float* s1 = s[2 * kf + 1];
            uint32_t pah[4];
            pah[0] = packh2(s0[0], s0[1]);
            pah[1] = packh2(s0[2], s0[3]);
            pah[2] = packh2(s1[0], s1[1]);
            pah[3] = packh2(s1[2], s1[3]);
            MMA16816(accL, pah, ONESH, ONESH);
#pragma unroll
            for (int dg = 0; dg < 4; dg++) {
                uint32_t vh[4];
                int r = kf * 16 + arow;
                LDM4T(vh, bV + (uint32_t)(r * 128 +
                          (((dg * 2 + chA) ^ (r & 7)) << 4)));
                MMA16816(accO[dg * 2],     pah, vh[0], vh[1]);
                MMA16816(accO[dg * 2 + 1], pah, vh[2], vh[3]);
            }
        }
    }

    // ---- epilogue ----
    const float i1 = 1.f / accL[0], i2 = 1.f / accL[2];
#pragma unroll
    for (int f = 0; f < 8; f++) {
        int col = head * DH_ + f * 8 + 2 * (lane & 3);
        size_t x1 = ((size_t)(b * N_ + gi1) * D_ + col) >> 1;
        size_t x2 = ((size_t)(b * N_ + gi2) * D_ + col) >> 1;
        AOhi[x1] = packh2(accO[f][0] * i1, accO[f][1] * i1);
        AOhi[x2] = packh2(accO[f][2] * i2, accO[f][3] * i2);
    }
}

// ============================================================================
extern "C" void kernel_launch(void* const* d_in, const int* in_sizes, int n_in,
                              void* d_out, int out_size)
{
    const float* x    = (const float*)d_in[0];
    const int*   mask = (const int*)d_in[1];
    const float* Wq   = (const float*)d_in[2];
    const float* Wk   = (const float*)d_in[3];
    const float* Wv   = (const float*)d_in[4];
    const float* Wfc  = (const float*)d_in[5];
    const float* bfc  = (const float*)d_in[6];
    float*       out  = (float*)d_out;

    uint32_t *Xhi, *Wqhi, *Wkvhi, *Wfhi, *Qhi, *Khi, *Vhi, *AOhi;
    cudaGetSymbolAddress((void**)&Xhi,   g_Xhi);
    cudaGetSymbolAddress((void**)&Wqhi,  g_Wqhi);
    cudaGetSymbolAddress((void**)&Wkvhi, g_Wkvhi);
    cudaGetSymbolAddress((void**)&Wfhi,  g_Wfhi);
    cudaGetSymbolAddress((void**)&Qhi,   g_Qhi);
    cudaGetSymbolAddress((void**)&Khi,   g_Khi);
    cudaGetSymbolAddress((void**)&Vhi,   g_Vhi);
    cudaGetSymbolAddress((void**)&AOhi,  g_AOhi);

    const int SM_GB = 3 * (128 + 128) * 128;   // 98304 -> 2 CTAs/SM
    const int SM_FL = 3 * 16384;               // 49152 -> 2 CTAs/SM
    cudaFuncSetAttribute((const void*)gemm_big<0>,
                         cudaFuncAttributeMaxDynamicSharedMemorySize, SM_GB);
    cudaFuncSetAttribute((const void*)gemm_big<1>,
                         cudaFuncAttributeMaxDynamicSharedMemorySize, SM_GB);
    cudaFuncSetAttribute((const void*)flash_h,
                         cudaFuncAttributeMaxDynamicSharedMemorySize, SM_FL);

    // 1. split all fp32 inputs -> packed fp16
    split_hi<<<(OTOT + 255) / 256, 256>>>(
        x, Wq, Wk, Wv, Wfc, Xhi, Wqhi, Wkvhi, Wfhi);

    // 2. merged Q/K/V projections: bx 0-7 -> Q (scaled), bx 8 -> K|V
    gemm_big<0><<<dim3(9, M_ / 128), 256, SM_GB>>>(
        Xhi, Wqhi, Wkvhi, nullptr, nullptr, Qhi, Khi, Vhi);

    // 3. flash attention (32-row q-tiles, 4 heads/CTA, 2 CTAs/SM) -> AO fp16
    flash_h<<<dim3(N_ / 32, H_ / 4, B_), 256, SM_FL>>>(
        Qhi, Khi, Vhi, mask, AOhi);

    // 4. out = AO Wfc^T + bfc
    gemm_big<1><<<dim3(D_ / 128, M_ / 128), 256, SM_GB>>>(
        AOhi, Wfhi, nullptr, bfc, out, nullptr, nullptr, nullptr);
}